// round 2
// baseline (speedup 1.0000x reference)
#include <cuda_runtime.h>
#include <math.h>

#define Bsz 32
#define Nf  4096
#define Kv  1024
#define Dm  1024
#define Hh  16
#define MAXF 4096

// Single static scratch arena (63 MB) — no allocations anywhere.
__device__ float g_scratch[16515072];

// ---------------- mean over frame tokens (split into 16 partials) -------------
__global__ void k_mean_part(const float* __restrict__ frame, float* __restrict__ mpart)
{
    int b = blockIdx.x, sp = blockIdx.y, tid = threadIdx.x;
    const float4* fp = (const float4*)(frame + ((size_t)b * Nf + sp * 256) * Dm) + tid;
    float4 acc = make_float4(0.f, 0.f, 0.f, 0.f);
    #pragma unroll 4
    for (int n = 0; n < 256; n++) {
        float4 v = fp[(size_t)n * 256];
        acc.x += v.x; acc.y += v.y; acc.z += v.z; acc.w += v.w;
    }
    ((float4*)(mpart + ((size_t)sp * Bsz + b) * Dm))[tid] = acc;
}

// ---------------- q init: stack(mean, max_init) + query_base + role + t_emb ---
__global__ void k_qinit(const float* __restrict__ mpart, const float* __restrict__ mi,
                        const float* __restrict__ qb, const float* __restrict__ role,
                        const float* __restrict__ tw, const int* __restrict__ fidx,
                        float* __restrict__ q)
{
    int b = blockIdx.x, tid = threadIdx.x;
    float4 m = make_float4(0.f, 0.f, 0.f, 0.f);
    for (int sp = 0; sp < 16; sp++) {
        float4 v = ((const float4*)(mpart + ((size_t)sp * Bsz + b) * Dm))[tid];
        m.x += v.x; m.y += v.y; m.z += v.z; m.w += v.w;
    }
    const float inv = 1.f / (float)Nf;
    int t = fidx[b]; t = t < 0 ? 0 : (t > MAXF - 1 ? MAXF - 1 : t);
    float4 te = ((const float4*)(tw + (size_t)t * Dm))[tid];
    float4 q0 = ((const float4*)qb)[tid];
    float4 q1 = ((const float4*)(qb + Dm))[tid];
    float4 r0 = ((const float4*)role)[tid];
    float4 r1 = ((const float4*)(role + Dm))[tid];
    float4 mv = ((const float4*)(mi + (size_t)b * Dm))[tid];
    float4 o0, o1;
    o0.x = m.x * inv + q0.x + r0.x + te.x;  o0.y = m.y * inv + q0.y + r0.y + te.y;
    o0.z = m.z * inv + q0.z + r0.z + te.z;  o0.w = m.w * inv + q0.w + r0.w + te.w;
    o1.x = mv.x + q1.x + r1.x + te.x;       o1.y = mv.y + q1.y + r1.y + te.y;
    o1.z = mv.z + q1.z + r1.z + te.z;       o1.w = mv.w + q1.w + r1.w + te.w;
    ((float4*)(q + (size_t)b * 2 * Dm))[tid] = o0;
    ((float4*)(q + (size_t)b * 2 * Dm + Dm))[tid] = o1;
}

// ---------------- LayerNorm over D=1024 (one block per row, 256 thr) ---------
__global__ void k_ln(const float* __restrict__ in, const float* __restrict__ g,
                     const float* __restrict__ b, float* __restrict__ outp)
{
    __shared__ float2 red[256];
    int row = blockIdx.x, tid = threadIdx.x;
    float4 v = ((const float4*)(in + (size_t)row * Dm))[tid];
    float s = v.x + v.y + v.z + v.w;
    float sq = v.x * v.x + v.y * v.y + v.z * v.z + v.w * v.w;
    red[tid] = make_float2(s, sq); __syncthreads();
    for (int st = 128; st > 0; st >>= 1) {
        if (tid < st) { red[tid].x += red[tid + st].x; red[tid].y += red[tid + st].y; }
        __syncthreads();
    }
    float mean = red[0].x * (1.f / 1024.f);
    float var  = red[0].y * (1.f / 1024.f) - mean * mean;
    float rstd = rsqrtf(var + 1e-5f);
    float4 gv = ((const float4*)g)[tid];
    float4 bv = ((const float4*)b)[tid];
    float4 o;
    o.x = (v.x - mean) * rstd * gv.x + bv.x;
    o.y = (v.y - mean) * rstd * gv.y + bv.y;
    o.z = (v.z - mean) * rstd * gv.z + bv.z;
    o.w = (v.w - mean) * rstd * gv.w + bv.w;
    ((float4*)(outp + (size_t)row * Dm))[tid] = o;
}

// ---------------- small GEMM: part[ks][m][n] = A[M,K] @ W[N,K]^T chunk -------
__global__ __launch_bounds__(256) void k_gemm_part(
    const float* __restrict__ A, int lda, int M,
    const float* __restrict__ W,
    float* __restrict__ part, int N, int K, int kchunk)
{
    __shared__ float As[16][64];
    __shared__ float Ws[16][64];
    int tid = threadIdx.x;
    int n0 = blockIdx.x * 64;
    int ks = blockIdx.y;
    int ty = tid >> 4, tx = tid & 15;
    int lm = tid >> 2;
    int lk = (tid & 3) << 2;
    float acc[4][4];
    #pragma unroll
    for (int i = 0; i < 4; i++)
        #pragma unroll
        for (int j = 0; j < 4; j++) acc[i][j] = 0.f;

    const float* Ap = A + (size_t)lm * lda;
    const float* Wp = W + (size_t)(n0 + lm) * K;
    int kend = ks * kchunk + kchunk;
    for (int kk = ks * kchunk; kk < kend; kk += 16) {
        float4 av = make_float4(0.f, 0.f, 0.f, 0.f);
        if (lm < M) av = *(const float4*)(Ap + kk + lk);
        float4 wv = *(const float4*)(Wp + kk + lk);
        __syncthreads();
        As[lk + 0][lm] = av.x; As[lk + 1][lm] = av.y; As[lk + 2][lm] = av.z; As[lk + 3][lm] = av.w;
        Ws[lk + 0][lm] = wv.x; Ws[lk + 1][lm] = wv.y; Ws[lk + 2][lm] = wv.z; Ws[lk + 3][lm] = wv.w;
        __syncthreads();
        #pragma unroll
        for (int k2 = 0; k2 < 16; k2++) {
            float4 a = *(const float4*)&As[k2][ty << 2];
            float4 w = *(const float4*)&Ws[k2][tx << 2];
            acc[0][0] += a.x * w.x; acc[0][1] += a.x * w.y; acc[0][2] += a.x * w.z; acc[0][3] += a.x * w.w;
            acc[1][0] += a.y * w.x; acc[1][1] += a.y * w.y; acc[1][2] += a.y * w.z; acc[1][3] += a.y * w.w;
            acc[2][0] += a.z * w.x; acc[2][1] += a.z * w.y; acc[2][2] += a.z * w.z; acc[2][3] += a.z * w.w;
            acc[3][0] += a.w * w.x; acc[3][1] += a.w * w.y; acc[3][2] += a.w * w.z; acc[3][3] += a.w * w.w;
        }
    }
    float* P = part + (size_t)ks * M * N;
    #pragma unroll
    for (int i = 0; i < 4; i++) {
        int m = (ty << 2) + i;
        if (m < M) {
            float* row = P + (size_t)m * N + n0 + (tx << 2);
            row[0] = acc[i][0]; row[1] = acc[i][1]; row[2] = acc[i][2]; row[3] = acc[i][3];
        }
    }
}

__device__ __forceinline__ float gelu_exact(float x)
{
    return 0.5f * x * (1.f + erff(x * 0.70710678118654752f));
}

// reduce split-K partials + bias (+ residual) (+ gelu) -> C (row stride ldc)
__global__ void k_gemm_reduce(const float* __restrict__ part,
                              float* __restrict__ C, int ldc,
                              const float* __restrict__ bias,
                              const float* __restrict__ Res, int ldr,
                              int M, int N, int nsplit, int act)
{
    int n = blockIdx.x * 256 + threadIdx.x;
    int m = blockIdx.y;
    if (n >= N) return;
    float s = 0.f;
    for (int ks = 0; ks < nsplit; ks++) s += part[((size_t)ks * M + m) * N + n];
    s += bias[n];
    if (Res) s += Res[(size_t)m * ldr + n];
    if (act) s = gelu_exact(s);
    C[(size_t)m * ldc + n] = s;
}

// ---------------- 2-token self-attention core (post in_proj) -----------------
__global__ void k_selfattn(const float* __restrict__ t3, float* __restrict__ attn)
{
    int b = blockIdx.x, h = blockIdx.y, d = threadIdx.x;
    const float* r0 = t3 + (size_t)(b * 2 + 0) * 3072;
    const float* r1 = t3 + (size_t)(b * 2 + 1) * 3072;
    int j = h * 64 + d;
    float q0 = r0[j], k0 = r0[1024 + j], v0 = r0[2048 + j];
    float q1 = r1[j], k1 = r1[1024 + j], v1 = r1[2048 + j];
    __shared__ float sh[4][64];
    sh[0][d] = q0 * k0; sh[1][d] = q0 * k1; sh[2][d] = q1 * k0; sh[3][d] = q1 * k1;
    __syncthreads();
    for (int st = 32; st > 0; st >>= 1) {
        if (d < st) {
            #pragma unroll
            for (int i = 0; i < 4; i++) sh[i][d] += sh[i][d + st];
        }
        __syncthreads();
    }
    float s00 = sh[0][0] * 0.125f, s01 = sh[1][0] * 0.125f;
    float s10 = sh[2][0] * 0.125f, s11 = sh[3][0] * 0.125f;
    float m0 = fmaxf(s00, s01), m1 = fmaxf(s10, s11);
    float e00 = expf(s00 - m0), e01 = expf(s01 - m0);
    float e10 = expf(s10 - m1), e11 = expf(s11 - m1);
    float a00 = e00 / (e00 + e01), a01 = e01 / (e00 + e01);
    float a10 = e10 / (e10 + e11), a11 = e11 / (e10 + e11);
    attn[(size_t)(b * 2 + 0) * Dm + j] = a00 * v0 + a01 * v1;
    attn[(size_t)(b * 2 + 1) * Dm + j] = a10 * v0 + a11 * v1;
}

// ---------------- fold: u[b,h,:] = qp[b, h*64: ] @ wk_h ----------------------
__global__ void k_ufold(const float* __restrict__ qp, const float* __restrict__ wk,
                        float* __restrict__ u)
{
    int h = blockIdx.x;
    int e = blockIdx.y * 128 + threadIdx.x;
    __shared__ float qs[32][64];
    for (int i = threadIdx.x; i < 2048; i += 128)
        qs[i >> 6][i & 63] = qp[(size_t)(i >> 6) * Dm + h * 64 + (i & 63)];
    __syncthreads();
    float acc[32];
    #pragma unroll
    for (int b2 = 0; b2 < 32; b2++) acc[b2] = 0.f;
    for (int d = 0; d < 64; d++) {
        float w = wk[(size_t)(h * 64 + d) * Dm + e];
        #pragma unroll
        for (int b2 = 0; b2 < 32; b2++) acc[b2] += qs[b2][d] * w;
    }
    #pragma unroll
    for (int b2 = 0; b2 < 32; b2++) u[((size_t)b2 * Hh + h) * Dm + e] = acc[b2];
}

// ---------------- scores: s[b,h,n] = 0.125 * X[b,n,:] . u[b,h,:] -------------
__global__ __launch_bounds__(256) void k_scores(
    const float* __restrict__ X, const float* __restrict__ u,
    float* __restrict__ s, int Nt)
{
    extern __shared__ float ush[];   // 16*1024 floats = 64 KB
    int b = blockIdx.x, tid = threadIdx.x;
    const float4* usrc = (const float4*)(u + (size_t)b * Hh * Dm);
    for (int i = tid; i < 4096; i += 256) ((float4*)ush)[i] = usrc[i];
    __syncthreads();
    int w = tid >> 5, lane = tid & 31;
    for (int tl = 0; tl < 8; tl++) {
        int n = blockIdx.y * 64 + tl * 8 + w;
        const float4* xp = (const float4*)(X + ((size_t)b * Nt + n) * Dm);
        float acc[16];
        #pragma unroll
        for (int h2 = 0; h2 < 16; h2++) acc[h2] = 0.f;
        #pragma unroll
        for (int i = 0; i < 8; i++) {
            float4 f = xp[i * 32 + lane];
            #pragma unroll
            for (int h2 = 0; h2 < 16; h2++) {
                float4 uv = *(const float4*)&ush[h2 * Dm + i * 128 + (lane << 2)];
                acc[h2] += f.x * uv.x + f.y * uv.y + f.z * uv.z + f.w * uv.w;
            }
        }
        #pragma unroll
        for (int h2 = 0; h2 < 16; h2++) {
            float vv = acc[h2];
            #pragma unroll
            for (int off = 16; off; off >>= 1) vv += __shfl_xor_sync(0xffffffffu, vv, off);
            if (lane == 0) s[((size_t)b * Hh + h2) * Nt + n] = vv * 0.125f;
        }
    }
}

// ---------------- row softmax over Nt (one block per (b,h)) ------------------
template <int CNT>
__global__ void k_softmax(float* __restrict__ s, int Nt)
{
    __shared__ float red[256];
    size_t base = (size_t)blockIdx.x * Nt;
    int tid = threadIdx.x;
    float v[CNT];
    float mx = -1e30f;
    #pragma unroll
    for (int i = 0; i < CNT; i++) { v[i] = s[base + i * 256 + tid]; mx = fmaxf(mx, v[i]); }
    red[tid] = mx; __syncthreads();
    for (int st = 128; st > 0; st >>= 1) {
        if (tid < st) red[tid] = fmaxf(red[tid], red[tid + st]);
        __syncthreads();
    }
    mx = red[0]; __syncthreads();
    float sum = 0.f;
    #pragma unroll
    for (int i = 0; i < CNT; i++) { v[i] = expf(v[i] - mx); sum += v[i]; }
    red[tid] = sum; __syncthreads();
    for (int st = 128; st > 0; st >>= 1) {
        if (tid < st) red[tid] += red[tid + st];
        __syncthreads();
    }
    float inv = 1.f / red[0];
    #pragma unroll
    for (int i = 0; i < CNT; i++) s[base + i * 256 + tid] = v[i] * inv;
}

// ---------------- wbar partials: part[sp][b][h][e] = sum_{n chunk} a*X -------
__global__ __launch_bounds__(256) void k_wbar_part(
    const float* __restrict__ X, const float* __restrict__ a,
    float* __restrict__ part, int Nt)
{
    __shared__ float ash[16][256];
    int b = blockIdx.x, sp = blockIdx.y;
    int n0 = sp * 256;
    int tid = threadIdx.x;
    for (int i = tid; i < 4096; i += 256)
        ash[i >> 8][i & 255] = a[((size_t)b * Hh + (i >> 8)) * Nt + n0 + (i & 255)];
    __syncthreads();
    float4 acc[16];
    #pragma unroll
    for (int h2 = 0; h2 < 16; h2++) acc[h2] = make_float4(0.f, 0.f, 0.f, 0.f);
    const float4* xp = (const float4*)(X + ((size_t)b * Nt + n0) * Dm) + tid;
    for (int nn = 0; nn < 256; nn++) {
        float4 f = xp[(size_t)nn * 256];
        #pragma unroll
        for (int h2 = 0; h2 < 16; h2++) {
            float av = ash[h2][nn];
            acc[h2].x += av * f.x; acc[h2].y += av * f.y;
            acc[h2].z += av * f.z; acc[h2].w += av * f.w;
        }
    }
    float4* P = (float4*)(part + (((size_t)sp * Bsz + b) * Hh) * Dm);
    #pragma unroll
    for (int h2 = 0; h2 < 16; h2++) P[h2 * 256 + tid] = acc[h2];
}

__global__ void k_wbar_reduce(const float* __restrict__ part, float* __restrict__ wbar, int NS)
{
    int idx = blockIdx.x * 256 + threadIdx.x;  // over 32*16*1024 = 524288
    float s = 0.f;
    for (int sp = 0; sp < NS; sp++) s += part[(size_t)sp * 524288 + idx];
    wbar[idx] = s;
}

// ---------------- v-projection: o[b, h*64+d] = wbar[b,h,:].wv[j,:] + bv[j] ---
__global__ void k_vproj(const float* __restrict__ wbar, const float* __restrict__ wv,
                        const float* __restrict__ bv, float* __restrict__ o)
{
    __shared__ float wsh[1024];
    int b = blockIdx.x, h = blockIdx.y, tid = threadIdx.x;
    ((float4*)wsh)[tid] = ((const float4*)(wbar + ((size_t)b * Hh + h) * Dm))[tid];
    __syncthreads();
    int w = tid >> 5, lane = tid & 31;
    for (int dd = w; dd < 64; dd += 8) {
        int j = h * 64 + dd;
        const float4* wvp = (const float4*)(wv + (size_t)j * Dm);
        float acc = 0.f;
        #pragma unroll
        for (int i = 0; i < 8; i++) {
            float4 a = wvp[i * 32 + lane];
            float4 c = *(const float4*)&wsh[i * 128 + (lane << 2)];
            acc += a.x * c.x + a.y * c.y + a.z * c.z + a.w * c.w;
        }
        #pragma unroll
        for (int off = 16; off; off >>= 1) acc += __shfl_xor_sync(0xffffffffu, acc, off);
        if (lane == 0) o[(size_t)b * Dm + j] = acc + bv[j];
    }
}

// ---------------- host helper: split-K GEMM via partials ---------------------
static void gemm(const float* A, int lda, int M, const float* W, int N, int K,
                 int splitK, const float* bias, const float* Res, int ldr,
                 float* C, int ldc, int act, float* part)
{
    dim3 g(N / 64, splitK);
    k_gemm_part<<<g, 256>>>(A, lda, M, W, part, N, K, K / splitK);
    dim3 gr((N + 255) / 256, M);
    k_gemm_reduce<<<gr, 256>>>(part, C, ldc, bias, Res, ldr, M, N, splitK, act);
}

extern "C" void kernel_launch(void* const* d_in, const int* in_sizes, int n_in,
                              void* d_out, int out_size)
{
    const float* frame = (const float*)d_in[0];
    const float* kvs   = (const float*)d_in[1];
    const float* maxi  = (const float*)d_in[2];
    const float* qbase = (const float*)d_in[3];
    const float* role  = (const float*)d_in[4];
    const float* timew = (const float*)d_in[5];
    const float* ln1g  = (const float*)d_in[6];
    const float* ln1b  = (const float*)d_in[7];
    const float* sa_in_w = (const float*)d_in[8];
    const float* sa_in_b = (const float*)d_in[9];
    const float* sa_out_w = (const float*)d_in[10];
    const float* sa_out_b = (const float*)d_in[11];
    const float* ln2g  = (const float*)d_in[12];
    const float* ln2b  = (const float*)d_in[13];
    const float* cg_in_w = (const float*)d_in[14];
    const float* cg_in_b = (const float*)d_in[15];
    const float* cg_out_w = (const float*)d_in[16];
    const float* cg_out_b = (const float*)d_in[17];
    const float* cs_in_w = (const float*)d_in[18];
    const float* cs_in_b = (const float*)d_in[19];
    const float* cs_out_w = (const float*)d_in[20];
    const float* cs_out_b = (const float*)d_in[21];
    const float* ln3g  = (const float*)d_in[22];
    const float* ln3b  = (const float*)d_in[23];
    const float* fw1   = (const float*)d_in[24];
    const float* fb1   = (const float*)d_in[25];
    const float* fw2   = (const float*)d_in[26];
    const float* fb2   = (const float*)d_in[27];
    const float* outg  = (const float*)d_in[28];
    const float* outb  = (const float*)d_in[29];
    const int*   fidx  = (const int*)d_in[30];
    float* outp = (float*)d_out;

    void* sp_;
    cudaGetSymbolAddress(&sp_, g_scratch);
    float* S = (float*)sp_;
    float* mpart = S;                   // 16*32*1024
    float* q     = mpart + 524288;      // 64*1024
    float* x     = q + 65536;           // 64*1024
    float* t3    = x + 65536;           // 64*3072
    float* attn  = t3 + 196608;         // 64*1024
    float* qpg   = attn + 65536;        // 32*1024
    float* qps   = qpg + 32768;         // 32*1024
    float* ug    = qps + 32768;         // 32*16*1024
    float* us    = ug + 524288;         // 32*16*1024
    float* sg    = us + 524288;         // 32*16*4096
    float* ss    = sg + 2097152;        // 32*16*1024
    float* wpart = ss + 524288;         // 16*32*16*1024
    float* wbarg = wpart + 8388608;     // 32*16*1024
    float* wbars = wbarg + 524288;      // 32*16*1024
    float* og    = wbars + 524288;      // 32*1024
    float* os    = og + 32768;          // 32*1024
    float* gpart = os + 32768;          // 2M floats gemm partials
    float* hh    = gpart + 2097152;     // 64*4096

    cudaFuncSetAttribute(k_scores, cudaFuncAttributeMaxDynamicSharedMemorySize, 65536);

    // init: mean + q assembly
    k_mean_part<<<dim3(32, 16), 256>>>(frame, mpart);
    k_qinit<<<32, 256>>>(mpart, maxi, qbase, role, timew, fidx, q);

    for (int l = 0; l < 2; l++) {
        const float* l1g = ln1g + l * Dm;   const float* l1b = ln1b + l * Dm;
        const float* siw = sa_in_w + (size_t)l * 3072 * Dm;
        const float* sib = sa_in_b + l * 3072;
        const float* sow = sa_out_w + (size_t)l * Dm * Dm;
        const float* sob = sa_out_b + l * Dm;
        const float* l2g = ln2g + l * Dm;   const float* l2b = ln2b + l * Dm;
        const float* giw = cg_in_w + (size_t)l * 3072 * Dm;
        const float* gib = cg_in_b + l * 3072;
        const float* gow = cg_out_w + (size_t)l * Dm * Dm;
        const float* gob = cg_out_b + l * Dm;
        const float* ciw = cs_in_w + (size_t)l * 3072 * Dm;
        const float* cib = cs_in_b + l * 3072;
        const float* cow = cs_out_w + (size_t)l * Dm * Dm;
        const float* cob = cs_out_b + l * Dm;
        const float* l3g = ln3g + l * Dm;   const float* l3b = ln3b + l * Dm;
        const float* w1 = fw1 + (size_t)l * 4096 * Dm;
        const float* b1 = fb1 + l * 4096;
        const float* w2 = fw2 + (size_t)l * Dm * 4096;
        const float* b2 = fb2 + l * Dm;

        // ---- self-attention (2 tokens) ----
        k_ln<<<64, 256>>>(q, l1g, l1b, x);
        gemm(x, 1024, 64, siw, 3072, 1024, 4, sib, nullptr, 0, t3, 3072, 0, gpart);
        k_selfattn<<<dim3(32, 16), 64>>>(t3, attn);
        gemm(attn, 1024, 64, sow, 1024, 1024, 8, sob, q, 1024, q, 1024, 0, gpart);

        // ---- cross-attention (folded K/V) ----
        k_ln<<<64, 256>>>(q, l2g, l2b, x);
        gemm(x,        2048, 32, giw, 1024, 1024, 8, gib, nullptr, 0, qpg, 1024, 0, gpart);
        gemm(x + 1024, 2048, 32, ciw, 1024, 1024, 8, cib, nullptr, 0, qps, 1024, 0, gpart);
        k_ufold<<<dim3(16, 8), 128>>>(qpg, giw + 1024 * 1024, ug);
        k_ufold<<<dim3(16, 8), 128>>>(qps, ciw + 1024 * 1024, us);
        k_scores<<<dim3(32, 64), 256, 65536>>>(frame, ug, sg, Nf);
        k_scores<<<dim3(32, 16), 256, 65536>>>(kvs, us, ss, Kv);
        k_softmax<16><<<512, 256>>>(sg, Nf);
        k_softmax<4><<<512, 256>>>(ss, Kv);
        k_wbar_part<<<dim3(32, 16), 256>>>(frame, sg, wpart, Nf);
        k_wbar_reduce<<<2048, 256>>>(wpart, wbarg, 16);
        k_wbar_part<<<dim3(32, 4), 256>>>(kvs, ss, wpart, Kv);
        k_wbar_reduce<<<2048, 256>>>(wpart, wbars, 4);
        k_vproj<<<dim3(32, 16), 256>>>(wbarg, giw + 2 * 1024 * 1024, gib + 2048, og);
        k_vproj<<<dim3(32, 16), 256>>>(wbars, ciw + 2 * 1024 * 1024, cib + 2048, os);
        gemm(og, 1024, 32, gow, 1024, 1024, 8, gob, q,        2048, q,        2048, 0, gpart);
        gemm(os, 1024, 32, cow, 1024, 1024, 8, cob, q + 1024, 2048, q + 1024, 2048, 0, gpart);

        // ---- FFN ----
        k_ln<<<64, 256>>>(q, l3g, l3b, x);
        gemm(x, 1024, 64, w1, 4096, 1024, 4, b1, nullptr, 0, hh, 4096, 1, gpart);
        gemm(hh, 4096, 64, w2, 1024, 4096, 8, b2, q, 1024, q, 1024, 0, gpart);
    }

    // final LN -> d_out (B,2,D) contiguous
    k_ln<<<64, 256>>>(q, outg, outb, outp);
}

// round 3
// speedup vs baseline: 2.3530x; 2.3530x over previous
#include <cuda_runtime.h>
#include <math.h>

#define Bsz 32
#define Nf  4096
#define Kv  1024
#define Dm  1024
#define Hh  16
#define MAXF 4096

typedef unsigned long long u64;

// Single static scratch arena — no allocations anywhere.
__device__ float g_scratch[16777216];

// ---- f32x2 packed helpers ---------------------------------------------------
__device__ __forceinline__ void ffma2(u64& d, u64 a, u64 b)
{
    asm("fma.rn.f32x2 %0, %1, %2, %0;" : "+l"(d) : "l"(a), "l"(b));
}
__device__ __forceinline__ u64 dup2(float a)
{
    u64 r; asm("mov.b64 %0, {%1,%1};" : "=l"(r) : "f"(a)); return r;
}
__device__ __forceinline__ float sum2(u64 v)
{
    float lo, hi; asm("mov.b64 {%0,%1}, %2;" : "=f"(lo), "=f"(hi) : "l"(v));
    return lo + hi;
}

// ---------------- mean over frame tokens (split into 16 partials) -------------
__global__ void k_mean_part(const float* __restrict__ frame, float* __restrict__ mpart)
{
    int b = blockIdx.x, sp = blockIdx.y, tid = threadIdx.x;
    const float4* fp = (const float4*)(frame + ((size_t)b * Nf + sp * 256) * Dm) + tid;
    float4 acc = make_float4(0.f, 0.f, 0.f, 0.f);
    #pragma unroll 4
    for (int n = 0; n < 256; n++) {
        float4 v = fp[(size_t)n * 256];
        acc.x += v.x; acc.y += v.y; acc.z += v.z; acc.w += v.w;
    }
    ((float4*)(mpart + ((size_t)sp * Bsz + b) * Dm))[tid] = acc;
}

// ---------------- q init ------------------------------------------------------
__global__ void k_qinit(const float* __restrict__ mpart, const float* __restrict__ mi,
                        const float* __restrict__ qb, const float* __restrict__ role,
                        const float* __restrict__ tw, const int* __restrict__ fidx,
                        float* __restrict__ q)
{
    int b = blockIdx.x, tid = threadIdx.x;
    float4 m = make_float4(0.f, 0.f, 0.f, 0.f);
    for (int sp = 0; sp < 16; sp++) {
        float4 v = ((const float4*)(mpart + ((size_t)sp * Bsz + b) * Dm))[tid];
        m.x += v.x; m.y += v.y; m.z += v.z; m.w += v.w;
    }
    const float inv = 1.f / (float)Nf;
    int t = fidx[b]; t = t < 0 ? 0 : (t > MAXF - 1 ? MAXF - 1 : t);
    float4 te = ((const float4*)(tw + (size_t)t * Dm))[tid];
    float4 q0 = ((const float4*)qb)[tid];
    float4 q1 = ((const float4*)(qb + Dm))[tid];
    float4 r0 = ((const float4*)role)[tid];
    float4 r1 = ((const float4*)(role + Dm))[tid];
    float4 mv = ((const float4*)(mi + (size_t)b * Dm))[tid];
    float4 o0, o1;
    o0.x = m.x * inv + q0.x + r0.x + te.x;  o0.y = m.y * inv + q0.y + r0.y + te.y;
    o0.z = m.z * inv + q0.z + r0.z + te.z;  o0.w = m.w * inv + q0.w + r0.w + te.w;
    o1.x = mv.x + q1.x + r1.x + te.x;       o1.y = mv.y + q1.y + r1.y + te.y;
    o1.z = mv.z + q1.z + r1.z + te.z;       o1.w = mv.w + q1.w + r1.w + te.w;
    ((float4*)(q + (size_t)b * 2 * Dm))[tid] = o0;
    ((float4*)(q + (size_t)b * 2 * Dm + Dm))[tid] = o1;
}

// ---------------- LayerNorm ---------------------------------------------------
__global__ void k_ln(const float* __restrict__ in, const float* __restrict__ g,
                     const float* __restrict__ b, float* __restrict__ outp)
{
    __shared__ float2 red[256];
    int row = blockIdx.x, tid = threadIdx.x;
    float4 v = ((const float4*)(in + (size_t)row * Dm))[tid];
    float s = v.x + v.y + v.z + v.w;
    float sq = v.x * v.x + v.y * v.y + v.z * v.z + v.w * v.w;
    red[tid] = make_float2(s, sq); __syncthreads();
    for (int st = 128; st > 0; st >>= 1) {
        if (tid < st) { red[tid].x += red[tid + st].x; red[tid].y += red[tid + st].y; }
        __syncthreads();
    }
    float mean = red[0].x * (1.f / 1024.f);
    float var  = red[0].y * (1.f / 1024.f) - mean * mean;
    float rstd = rsqrtf(var + 1e-5f);
    float4 gv = ((const float4*)g)[tid];
    float4 bv = ((const float4*)b)[tid];
    float4 o;
    o.x = (v.x - mean) * rstd * gv.x + bv.x;
    o.y = (v.y - mean) * rstd * gv.y + bv.y;
    o.z = (v.z - mean) * rstd * gv.z + bv.z;
    o.w = (v.w - mean) * rstd * gv.w + bv.w;
    ((float4*)(outp + (size_t)row * Dm))[tid] = o;
}

// ---------------- small GEMM: part[ks][m][n] = A[M,K] @ W[N,K]^T chunk -------
__global__ __launch_bounds__(256) void k_gemm_part(
    const float* __restrict__ A, int lda, int M,
    const float* __restrict__ W,
    float* __restrict__ part, int N, int K, int kchunk)
{
    __shared__ float As[16][64];
    __shared__ float Ws[16][64];
    int tid = threadIdx.x;
    int n0 = blockIdx.x * 64;
    int ks = blockIdx.y;
    int ty = tid >> 4, tx = tid & 15;
    int lm = tid >> 2;
    int lk = (tid & 3) << 2;
    u64 acc[4][2];
    #pragma unroll
    for (int i = 0; i < 4; i++) { acc[i][0] = 0ULL; acc[i][1] = 0ULL; }

    const float* Ap = A + (size_t)lm * lda;
    const float* Wp = W + (size_t)(n0 + lm) * K;
    int kend = ks * kchunk + kchunk;
    for (int kk = ks * kchunk; kk < kend; kk += 16) {
        float4 av = make_float4(0.f, 0.f, 0.f, 0.f);
        if (lm < M) av = *(const float4*)(Ap + kk + lk);
        float4 wv = *(const float4*)(Wp + kk + lk);
        __syncthreads();
        As[lk + 0][lm] = av.x; As[lk + 1][lm] = av.y; As[lk + 2][lm] = av.z; As[lk + 3][lm] = av.w;
        Ws[lk + 0][lm] = wv.x; Ws[lk + 1][lm] = wv.y; Ws[lk + 2][lm] = wv.z; Ws[lk + 3][lm] = wv.w;
        __syncthreads();
        #pragma unroll
        for (int k2 = 0; k2 < 16; k2++) {
            float4 a = *(const float4*)&As[k2][ty << 2];
            ulonglong2 w = *(const ulonglong2*)&Ws[k2][tx << 2];
            u64 d0 = dup2(a.x), d1 = dup2(a.y), d2 = dup2(a.z), d3 = dup2(a.w);
            ffma2(acc[0][0], d0, w.x); ffma2(acc[0][1], d0, w.y);
            ffma2(acc[1][0], d1, w.x); ffma2(acc[1][1], d1, w.y);
            ffma2(acc[2][0], d2, w.x); ffma2(acc[2][1], d2, w.y);
            ffma2(acc[3][0], d3, w.x); ffma2(acc[3][1], d3, w.y);
        }
    }
    float* P = part + (size_t)ks * M * N;
    #pragma unroll
    for (int i = 0; i < 4; i++) {
        int m = (ty << 2) + i;
        if (m < M) {
            ulonglong2* row = (ulonglong2*)(P + (size_t)m * N + n0 + (tx << 2));
            ulonglong2 v; v.x = acc[i][0]; v.y = acc[i][1];
            *row = v;
        }
    }
}

__device__ __forceinline__ float gelu_exact(float x)
{
    return 0.5f * x * (1.f + erff(x * 0.70710678118654752f));
}

__global__ void k_gemm_reduce(const float* __restrict__ part,
                              float* __restrict__ C, int ldc,
                              const float* __restrict__ bias,
                              const float* __restrict__ Res, int ldr,
                              int M, int N, int nsplit, int act)
{
    int n = blockIdx.x * 256 + threadIdx.x;
    int m = blockIdx.y;
    if (n >= N) return;
    float s = 0.f;
    for (int ks = 0; ks < nsplit; ks++) s += part[((size_t)ks * M + m) * N + n];
    s += bias[n];
    if (Res) s += Res[(size_t)m * ldr + n];
    if (act) s = gelu_exact(s);
    C[(size_t)m * ldc + n] = s;
}

// ---------------- 2-token self-attention core --------------------------------
__global__ void k_selfattn(const float* __restrict__ t3, float* __restrict__ attn)
{
    int b = blockIdx.x, h = blockIdx.y, d = threadIdx.x;
    const float* r0 = t3 + (size_t)(b * 2 + 0) * 3072;
    const float* r1 = t3 + (size_t)(b * 2 + 1) * 3072;
    int j = h * 64 + d;
    float q0 = r0[j], k0 = r0[1024 + j], v0 = r0[2048 + j];
    float q1 = r1[j], k1 = r1[1024 + j], v1 = r1[2048 + j];
    __shared__ float sh[4][64];
    sh[0][d] = q0 * k0; sh[1][d] = q0 * k1; sh[2][d] = q1 * k0; sh[3][d] = q1 * k1;
    __syncthreads();
    for (int st = 32; st > 0; st >>= 1) {
        if (d < st) {
            #pragma unroll
            for (int i = 0; i < 4; i++) sh[i][d] += sh[i][d + st];
        }
        __syncthreads();
    }
    float s00 = sh[0][0] * 0.125f, s01 = sh[1][0] * 0.125f;
    float s10 = sh[2][0] * 0.125f, s11 = sh[3][0] * 0.125f;
    float m0 = fmaxf(s00, s01), m1 = fmaxf(s10, s11);
    float e00 = expf(s00 - m0), e01 = expf(s01 - m0);
    float e10 = expf(s10 - m1), e11 = expf(s11 - m1);
    float a00 = e00 / (e00 + e01), a01 = e01 / (e00 + e01);
    float a10 = e10 / (e10 + e11), a11 = e11 / (e10 + e11);
    attn[(size_t)(b * 2 + 0) * Dm + j] = a00 * v0 + a01 * v1;
    attn[(size_t)(b * 2 + 1) * Dm + j] = a10 * v0 + a11 * v1;
}

// ---------------- fold: u[b,h,:] = qp[b, h*64: ] @ wk_h ----------------------
__global__ void k_ufold(const float* __restrict__ qp, const float* __restrict__ wk,
                        float* __restrict__ u)
{
    int h = blockIdx.x;
    int e = blockIdx.y * 128 + threadIdx.x;
    __shared__ float qs[32][64];
    for (int i = threadIdx.x; i < 2048; i += 128)
        qs[i >> 6][i & 63] = qp[(size_t)(i >> 6) * Dm + h * 64 + (i & 63)];
    __syncthreads();
    float acc[32];
    #pragma unroll
    for (int b2 = 0; b2 < 32; b2++) acc[b2] = 0.f;
    for (int d = 0; d < 64; d++) {
        float w = wk[(size_t)(h * 64 + d) * Dm + e];
        #pragma unroll
        for (int b2 = 0; b2 < 32; b2++) acc[b2] += qs[b2][d] * w;
    }
    #pragma unroll
    for (int b2 = 0; b2 < 32; b2++) u[((size_t)b2 * Hh + h) * Dm + e] = acc[b2];
}

// ---------------- scores: s[b,h,n] = 0.125 * X[b,n,:] . u[b,h,:] -------------
// 4 tokens per warp iteration; u in shared (64KB); f32x2 accumulation.
__global__ __launch_bounds__(256) void k_scores(
    const float* __restrict__ X, const float* __restrict__ u,
    float* __restrict__ s, int Nt)
{
    extern __shared__ float ush[];   // 16*1024 floats = 64 KB
    int b = blockIdx.x, tid = threadIdx.x;
    const float4* usrc = (const float4*)(u + (size_t)b * Hh * Dm);
    #pragma unroll
    for (int i = 0; i < 16; i++) ((float4*)ush)[tid + i * 256] = usrc[tid + i * 256];
    __syncthreads();
    int w = tid >> 5, lane = tid & 31;
    for (int tl = 0; tl < 2; tl++) {
        int n0 = blockIdx.y * 64 + tl * 32 + w * 4;
        const ulonglong2* xp = (const ulonglong2*)(X + ((size_t)b * Nt + n0) * Dm);
        u64 acc[16][4];
        #pragma unroll
        for (int h = 0; h < 16; h++)
            #pragma unroll
            for (int t = 0; t < 4; t++) acc[h][t] = 0ULL;
        for (int i = 0; i < 8; i++) {
            ulonglong2 x0 = xp[0 * 256 + i * 32 + lane];
            ulonglong2 x1 = xp[1 * 256 + i * 32 + lane];
            ulonglong2 x2 = xp[2 * 256 + i * 32 + lane];
            ulonglong2 x3 = xp[3 * 256 + i * 32 + lane];
            #pragma unroll
            for (int h = 0; h < 16; h++) {
                ulonglong2 uv = *(const ulonglong2*)&ush[h * Dm + i * 128 + (lane << 2)];
                ffma2(acc[h][0], x0.x, uv.x); ffma2(acc[h][0], x0.y, uv.y);
                ffma2(acc[h][1], x1.x, uv.x); ffma2(acc[h][1], x1.y, uv.y);
                ffma2(acc[h][2], x2.x, uv.x); ffma2(acc[h][2], x2.y, uv.y);
                ffma2(acc[h][3], x3.x, uv.x); ffma2(acc[h][3], x3.y, uv.y);
            }
        }
        #pragma unroll
        for (int h = 0; h < 16; h++) {
            #pragma unroll
            for (int t = 0; t < 4; t++) {
                float v = sum2(acc[h][t]);
                #pragma unroll
                for (int off = 16; off; off >>= 1) v += __shfl_xor_sync(0xffffffffu, v, off);
                if (lane == 0) s[((size_t)b * Hh + h) * Nt + n0 + t] = v * 0.125f;
            }
        }
    }
}

// ---------------- row softmax over Nt ----------------------------------------
template <int CNT>
__global__ void k_softmax(float* __restrict__ s, int Nt)
{
    __shared__ float red[256];
    size_t base = (size_t)blockIdx.x * Nt;
    int tid = threadIdx.x;
    float v[CNT];
    float mx = -1e30f;
    #pragma unroll
    for (int i = 0; i < CNT; i++) { v[i] = s[base + i * 256 + tid]; mx = fmaxf(mx, v[i]); }
    red[tid] = mx; __syncthreads();
    for (int st = 128; st > 0; st >>= 1) {
        if (tid < st) red[tid] = fmaxf(red[tid], red[tid + st]);
        __syncthreads();
    }
    mx = red[0]; __syncthreads();
    float sum = 0.f;
    #pragma unroll
    for (int i = 0; i < CNT; i++) { v[i] = expf(v[i] - mx); sum += v[i]; }
    red[tid] = sum; __syncthreads();
    for (int st = 128; st > 0; st >>= 1) {
        if (tid < st) red[tid] += red[tid + st];
        __syncthreads();
    }
    float inv = 1.f / red[0];
    #pragma unroll
    for (int i = 0; i < CNT; i++) s[base + i * 256 + tid] = v[i] * inv;
}

// ---------------- wbar partials: part[sp][b][h][e] = sum_{n chunk} a*X -------
// a-values pre-duplicated as (a,a) pairs in padded shared; f32x2 inner loop.
__global__ __launch_bounds__(256) void k_wbar_part(
    const float* __restrict__ X, const float* __restrict__ a,
    float* __restrict__ part, int Nt)
{
    __shared__ u64 ash2[256][17];
    int b = blockIdx.x, sp = blockIdx.y;
    int n0 = sp * 256;
    int tid = threadIdx.x;
    for (int idx = tid; idx < 4096; idx += 256) {
        int nn = idx & 255, h = idx >> 8;
        float av = a[((size_t)b * Hh + h) * Nt + n0 + nn];
        ash2[nn][h] = dup2(av);
    }
    __syncthreads();
    u64 acc[16][2];
    #pragma unroll
    for (int h = 0; h < 16; h++) { acc[h][0] = 0ULL; acc[h][1] = 0ULL; }
    const ulonglong2* xp = (const ulonglong2*)(X + ((size_t)b * Nt + n0) * Dm) + tid;
    for (int nn = 0; nn < 256; nn++) {
        ulonglong2 f = xp[(size_t)nn * 256];
        #pragma unroll
        for (int h = 0; h < 16; h++) {
            u64 aa = ash2[nn][h];
            ffma2(acc[h][0], aa, f.x);
            ffma2(acc[h][1], aa, f.y);
        }
    }
    ulonglong2* P = (ulonglong2*)(part + (((size_t)sp * Bsz + b) * Hh) * Dm);
    #pragma unroll
    for (int h = 0; h < 16; h++) {
        ulonglong2 v; v.x = acc[h][0]; v.y = acc[h][1];
        P[h * 256 + tid] = v;
    }
}

// ---------------- v-projection (fused split reduce) --------------------------
__global__ void k_vproj(const float* __restrict__ part, int NS,
                        const float* __restrict__ wv,
                        const float* __restrict__ bv, float* __restrict__ o)
{
    __shared__ float wsh[1024];
    int b = blockIdx.x, h = blockIdx.y, tid = threadIdx.x;
    float4 acc4 = make_float4(0.f, 0.f, 0.f, 0.f);
    for (int sp = 0; sp < NS; sp++) {
        float4 v = ((const float4*)(part + (((size_t)sp * Bsz + b) * Hh + h) * Dm))[tid];
        acc4.x += v.x; acc4.y += v.y; acc4.z += v.z; acc4.w += v.w;
    }
    ((float4*)wsh)[tid] = acc4;
    __syncthreads();
    int w = tid >> 5, lane = tid & 31;
    for (int dd = w; dd < 64; dd += 8) {
        int j = h * 64 + dd;
        const float4* wvp = (const float4*)(wv + (size_t)j * Dm);
        float acc = 0.f;
        #pragma unroll
        for (int i = 0; i < 8; i++) {
            float4 a = wvp[i * 32 + lane];
            float4 c = *(const float4*)&wsh[i * 128 + (lane << 2)];
            acc += a.x * c.x + a.y * c.y + a.z * c.z + a.w * c.w;
        }
        #pragma unroll
        for (int off = 16; off; off >>= 1) acc += __shfl_xor_sync(0xffffffffu, acc, off);
        if (lane == 0) o[(size_t)b * Dm + j] = acc + bv[j];
    }
}

// ---------------- host helper: split-K GEMM via partials ---------------------
static void gemm(const float* A, int lda, int M, const float* W, int N, int K,
                 int splitK, const float* bias, const float* Res, int ldr,
                 float* C, int ldc, int act, float* part)
{
    dim3 g(N / 64, splitK);
    k_gemm_part<<<g, 256>>>(A, lda, M, W, part, N, K, K / splitK);
    dim3 gr((N + 255) / 256, M);
    k_gemm_reduce<<<gr, 256>>>(part, C, ldc, bias, Res, ldr, M, N, splitK, act);
}

extern "C" void kernel_launch(void* const* d_in, const int* in_sizes, int n_in,
                              void* d_out, int out_size)
{
    const float* frame = (const float*)d_in[0];
    const float* kvs   = (const float*)d_in[1];
    const float* maxi  = (const float*)d_in[2];
    const float* qbase = (const float*)d_in[3];
    const float* role  = (const float*)d_in[4];
    const float* timew = (const float*)d_in[5];
    const float* ln1g  = (const float*)d_in[6];
    const float* ln1b  = (const float*)d_in[7];
    const float* sa_in_w = (const float*)d_in[8];
    const float* sa_in_b = (const float*)d_in[9];
    const float* sa_out_w = (const float*)d_in[10];
    const float* sa_out_b = (const float*)d_in[11];
    const float* ln2g  = (const float*)d_in[12];
    const float* ln2b  = (const float*)d_in[13];
    const float* cg_in_w = (const float*)d_in[14];
    const float* cg_in_b = (const float*)d_in[15];
    const float* cg_out_w = (const float*)d_in[16];
    const float* cg_out_b = (const float*)d_in[17];
    const float* cs_in_w = (const float*)d_in[18];
    const float* cs_in_b = (const float*)d_in[19];
    const float* cs_out_w = (const float*)d_in[20];
    const float* cs_out_b = (const float*)d_in[21];
    const float* ln3g  = (const float*)d_in[22];
    const float* ln3b  = (const float*)d_in[23];
    const float* fw1   = (const float*)d_in[24];
    const float* fb1   = (const float*)d_in[25];
    const float* fw2   = (const float*)d_in[26];
    const float* fb2   = (const float*)d_in[27];
    const float* outg  = (const float*)d_in[28];
    const float* outb  = (const float*)d_in[29];
    const int*   fidx  = (const int*)d_in[30];
    float* outp = (float*)d_out;

    void* sp_;
    cudaGetSymbolAddress(&sp_, g_scratch);
    float* S = (float*)sp_;
    float* mpart = S;                   // 524288
    float* q     = mpart + 524288;      // 65536
    float* x     = q + 65536;           // 65536
    float* t3    = x + 65536;           // 196608
    float* attn  = t3 + 196608;         // 65536
    float* qpg   = attn + 65536;        // 32768
    float* qps   = qpg + 32768;         // 32768
    float* ug    = qps + 32768;         // 524288
    float* us    = ug + 524288;         // 524288
    float* sg    = us + 524288;         // 2097152
    float* ss    = sg + 2097152;        // 524288
    float* wpart = ss + 524288;         // 8388608
    float* og    = wpart + 8388608;     // 32768
    float* os    = og + 32768;          // 32768
    float* gpart = os + 32768;          // 3276800
    float* hh    = gpart + 3276800;     // 262144

    cudaFuncSetAttribute(k_scores, cudaFuncAttributeMaxDynamicSharedMemorySize, 65536);

    // init: mean + q assembly
    k_mean_part<<<dim3(32, 16), 256>>>(frame, mpart);
    k_qinit<<<32, 256>>>(mpart, maxi, qbase, role, timew, fidx, q);

    for (int l = 0; l < 2; l++) {
        const float* l1g = ln1g + l * Dm;   const float* l1b = ln1b + l * Dm;
        const float* siw = sa_in_w + (size_t)l * 3072 * Dm;
        const float* sib = sa_in_b + l * 3072;
        const float* sow = sa_out_w + (size_t)l * Dm * Dm;
        const float* sob = sa_out_b + l * Dm;
        const float* l2g = ln2g + l * Dm;   const float* l2b = ln2b + l * Dm;
        const float* giw = cg_in_w + (size_t)l * 3072 * Dm;
        const float* gib = cg_in_b + l * 3072;
        const float* gow = cg_out_w + (size_t)l * Dm * Dm;
        const float* gob = cg_out_b + l * Dm;
        const float* ciw = cs_in_w + (size_t)l * 3072 * Dm;
        const float* cib = cs_in_b + l * 3072;
        const float* cow = cs_out_w + (size_t)l * Dm * Dm;
        const float* cob = cs_out_b + l * Dm;
        const float* l3g = ln3g + l * Dm;   const float* l3b = ln3b + l * Dm;
        const float* w1 = fw1 + (size_t)l * 4096 * Dm;
        const float* b1 = fb1 + l * 4096;
        const float* w2 = fw2 + (size_t)l * Dm * 4096;
        const float* b2 = fb2 + l * Dm;

        // ---- self-attention (2 tokens) ----
        k_ln<<<64, 256>>>(q, l1g, l1b, x);
        gemm(x, 1024, 64, siw, 3072, 1024, 16, sib, nullptr, 0, t3, 3072, 0, gpart);
        k_selfattn<<<dim3(32, 16), 64>>>(t3, attn);
        gemm(attn, 1024, 64, sow, 1024, 1024, 16, sob, q, 1024, q, 1024, 0, gpart);

        // ---- cross-attention (folded K/V) ----
        k_ln<<<64, 256>>>(q, l2g, l2b, x);
        gemm(x,        2048, 32, giw, 1024, 1024, 16, gib, nullptr, 0, qpg, 1024, 0, gpart);
        gemm(x + 1024, 2048, 32, ciw, 1024, 1024, 16, cib, nullptr, 0, qps, 1024, 0, gpart);
        k_ufold<<<dim3(16, 8), 128>>>(qpg, giw + 1024 * 1024, ug);
        k_ufold<<<dim3(16, 8), 128>>>(qps, ciw + 1024 * 1024, us);
        k_scores<<<dim3(32, 64), 256, 65536>>>(frame, ug, sg, Nf);
        k_scores<<<dim3(32, 16), 256, 65536>>>(kvs, us, ss, Kv);
        k_softmax<16><<<512, 256>>>(sg, Nf);
        k_softmax<4><<<512, 256>>>(ss, Kv);
        k_wbar_part<<<dim3(32, 16), 256>>>(frame, sg, wpart, Nf);
        k_vproj<<<dim3(32, 16), 256>>>(wpart, 16, giw + 2 * 1024 * 1024, gib + 2048, og);
        k_wbar_part<<<dim3(32, 4), 256>>>(kvs, ss, wpart, Kv);
        k_vproj<<<dim3(32, 16), 256>>>(wpart, 4, ciw + 2 * 1024 * 1024, cib + 2048, os);
        gemm(og, 1024, 32, gow, 1024, 1024, 16, gob, q,        2048, q,        2048, 0, gpart);
        gemm(os, 1024, 32, cow, 1024, 1024, 16, cob, q + 1024, 2048, q + 1024, 2048, 0, gpart);

        // ---- FFN ----
        k_ln<<<64, 256>>>(q, l3g, l3b, x);
        gemm(x, 1024, 64, w1, 4096, 1024, 8, b1, nullptr, 0, hh, 4096, 1, gpart);
        gemm(hh, 4096, 64, w2, 1024, 4096, 32, b2, q, 1024, q, 1024, 0, gpart);
    }

    // final LN -> d_out (B,2,D) contiguous
    k_ln<<<64, 256>>>(q, outg, outb, outp);
}